// round 4
// baseline (speedup 1.0000x reference)
#include <cuda_runtime.h>
#include <cuda_bf16.h>
#include <cstdint>
#include <cstddef>

#define T_STEPS 512
#define B_SZ    128
#define E_SEQ   768
#define COND    256
#define H_DIM   1024
#define KIN     1024
#define G3      3072
#define M_TOT   (T_STEPS * B_SZ)
#define NBLK    128

// ---------------- static device scratch --------------------------------------
__device__ float          g_gx[(size_t)M_TOT * G3];
__device__ __nv_bfloat16  g_whh_hi[(size_t)G3 * H_DIM];
__device__ __nv_bfloat16  g_whh_lo[(size_t)G3 * H_DIM];
__device__ __nv_bfloat16  g_wih_hi[(size_t)G3 * KIN];
__device__ __nv_bfloat16  g_wih_lo[(size_t)G3 * KIN];
__device__ __nv_bfloat16  g_xhi[(size_t)M_TOT * KIN];
__device__ __nv_bfloat16  g_xlo[(size_t)M_TOT * KIN];
__device__ __nv_bfloat16  g_hhi[2][B_SZ * H_DIM];
__device__ __nv_bfloat16  g_hlo[2][B_SZ * H_DIM];
__device__ unsigned       g_count;

// ---------------- prep kernels ------------------------------------------------
__global__ void k_init() { if (threadIdx.x == 0 && blockIdx.x == 0) g_count = 0; }

__global__ void k_split_whh(const float* __restrict__ w) {
    int i = blockIdx.x * blockDim.x + threadIdx.x;
    if (i < G3 * H_DIM) {
        float v = w[i];
        __nv_bfloat16 hi = __float2bfloat16(v);
        g_whh_hi[i] = hi;
        g_whh_lo[i] = __float2bfloat16(v - __bfloat162float(hi));
    }
}
__global__ void k_split_wih(const float* __restrict__ w) {
    int i = blockIdx.x * blockDim.x + threadIdx.x;
    if (i < G3 * KIN) {
        float v = w[i];
        __nv_bfloat16 hi = __float2bfloat16(v);
        g_wih_hi[i] = hi;
        g_wih_lo[i] = __float2bfloat16(v - __bfloat162float(hi));
    }
}

__global__ void k_split_x(const float* __restrict__ seq, const float* __restrict__ word) {
    size_t i = (size_t)blockIdx.x * blockDim.x + threadIdx.x;
    if (i >= (size_t)M_TOT * KIN / 4) return;
    int m  = (int)(i >> 8);
    int kq = (int)(i & 255);
    float4 v;
    if (kq < 64) v = ((const float4*)word)[(m & (B_SZ - 1)) * 64 + kq];
    else         v = ((const float4*)seq)[(size_t)m * 192 + (kq - 64)];
    float f[4] = {v.x, v.y, v.z, v.w};
    __nv_bfloat162 ph0, ph1, pl0, pl1;
    ph0.x = __float2bfloat16(f[0]); ph0.y = __float2bfloat16(f[1]);
    ph1.x = __float2bfloat16(f[2]); ph1.y = __float2bfloat16(f[3]);
    pl0.x = __float2bfloat16(f[0] - __bfloat162float(ph0.x));
    pl0.y = __float2bfloat16(f[1] - __bfloat162float(ph0.y));
    pl1.x = __float2bfloat16(f[2] - __bfloat162float(ph1.x));
    pl1.y = __float2bfloat16(f[3] - __bfloat162float(ph1.y));
    ((__nv_bfloat162*)g_xhi)[2 * i]     = ph0;
    ((__nv_bfloat162*)g_xhi)[2 * i + 1] = ph1;
    ((__nv_bfloat162*)g_xlo)[2 * i]     = pl0;
    ((__nv_bfloat162*)g_xlo)[2 * i + 1] = pl1;
}

// ---------------- PTX helpers (base-arch only: sm_80-class) -------------------
__device__ __forceinline__ unsigned smem_u32(const void* p) {
    return (unsigned)__cvta_generic_to_shared(p);
}
__device__ __forceinline__ void cp16(unsigned dst, const void* src) {
    asm volatile("cp.async.cg.shared.global [%0], [%1], 16;\n" :: "r"(dst), "l"(src));
}
#define CP_COMMIT()  asm volatile("cp.async.commit_group;\n")
#define CP_WAIT(n)   asm volatile("cp.async.wait_group %0;\n" :: "n"(n))

__device__ __forceinline__ void ldm4(unsigned r[4], unsigned addr) {
    asm volatile("ldmatrix.sync.aligned.m8n8.x4.shared.b16 {%0,%1,%2,%3}, [%4];"
        : "=r"(r[0]), "=r"(r[1]), "=r"(r[2]), "=r"(r[3]) : "r"(addr));
}

__device__ __forceinline__ void mma16816(float c[4], unsigned a0, unsigned a1,
                                         unsigned a2, unsigned a3,
                                         unsigned b0, unsigned b1) {
    asm volatile(
        "mma.sync.aligned.m16n8k16.row.col.f32.bf16.bf16.f32 "
        "{%0,%1,%2,%3},{%4,%5,%6,%7},{%8,%9},{%0,%1,%2,%3};\n"
        : "+f"(c[0]), "+f"(c[1]), "+f"(c[2]), "+f"(c[3])
        : "r"(a0), "r"(a1), "r"(a2), "r"(a3), "r"(b0), "r"(b1));
}

// ---------------- gx GEMM via raw mma.sync ------------------------------------
// CTA 128(M)x128(N), K chunks of 64 bf16. smem rows padded to 144B (36 words:
// row r start bank = 4r mod 32 -> 8-row ldmatrix reads conflict-free, no swizzle).
// Stage = 4 tiles (Ahi, Alo, Bhi, Blo) x 128 rows x 144B = 73728 B; 2 stages.
#define ROWB    144
#define TILEB   (128 * ROWB)
#define STAGEB  (4 * TILEB)
#define GXS_SMEM (2 * STAGEB)       // 147456

__global__ __launch_bounds__(256) void k_gx_mma() {
    extern __shared__ __align__(16) char dyn[];
    const unsigned dynb = smem_u32(dyn);

    const int tid = threadIdx.x;
    const int wid = tid >> 5, lid = tid & 31;
    const int wm = wid & 3, wn = wid >> 2;           // 4x2 warp grid, warp = 32m x 64n
    const int n0 = blockIdx.x * 128;
    const int m0 = blockIdx.y * 128;

    float acc[2][8][4];
    #pragma unroll
    for (int mt = 0; mt < 2; mt++)
        #pragma unroll
        for (int nt = 0; nt < 8; nt++)
            #pragma unroll
            for (int c = 0; c < 4; c++) acc[mt][nt][c] = 0.0f;

    auto load_chunk = [&](int c, int s) {
        const int k0 = c * 64;
        const unsigned sb = dynb + s * STAGEB;
        #pragma unroll
        for (int it = 0; it < 16; it++) {
            int i = tid + it * 256;          // 0..4095
            int t = i >> 10;                 // tile 0..3
            int r = (i >> 3) & 127;
            int q = i & 7;
            const __nv_bfloat16* src;
            if      (t == 0) src = g_xhi    + (size_t)(m0 + r) * KIN + k0 + q * 8;
            else if (t == 1) src = g_xlo    + (size_t)(m0 + r) * KIN + k0 + q * 8;
            else if (t == 2) src = g_wih_hi + (size_t)(n0 + r) * KIN + k0 + q * 8;
            else             src = g_wih_lo + (size_t)(n0 + r) * KIN + k0 + q * 8;
            cp16(sb + t * TILEB + r * ROWB + q * 16, src);
        }
        CP_COMMIT();
    };

    // per-lane ldmatrix address pieces: row (lane&15), col-half (lane>>4)*16B
    const int lrow = lid & 15;
    const int lcol = (lid >> 4) * 16;

    load_chunk(0, 0);

    for (int c = 0; c < 16; c++) {
        if (c < 15) { load_chunk(c + 1, (c + 1) & 1); CP_WAIT(1); }
        else        { CP_WAIT(0); }
        __syncthreads();

        const unsigned sb  = dynb + (c & 1) * STAGEB;
        const unsigned aHi = sb;
        const unsigned aLo = sb + TILEB;
        const unsigned bHi = sb + 2 * TILEB;
        const unsigned bLo = sb + 3 * TILEB;

        #pragma unroll
        for (int k16 = 0; k16 < 4; k16++) {
            const unsigned kb = k16 * 32 + lcol;
            unsigned ah[2][4], al[2][4], bh[4][4], bl[4][4];
            #pragma unroll
            for (int mt = 0; mt < 2; mt++) {
                unsigned ro = (wm * 32 + mt * 16 + lrow) * ROWB + kb;
                ldm4(ah[mt], aHi + ro);
                ldm4(al[mt], aLo + ro);
            }
            #pragma unroll
            for (int j = 0; j < 4; j++) {
                unsigned ro = (wn * 64 + j * 16 + lrow) * ROWB + kb;
                ldm4(bh[j], bHi + ro);
                ldm4(bl[j], bLo + ro);
            }
            #pragma unroll
            for (int mt = 0; mt < 2; mt++)
                #pragma unroll
                for (int j = 0; j < 4; j++) {
                    // n8 tile 2j: b regs {r0,r2}; tile 2j+1: {r1,r3}
                    mma16816(acc[mt][2*j],   ah[mt][0], ah[mt][1], ah[mt][2], ah[mt][3], bh[j][0], bh[j][2]);
                    mma16816(acc[mt][2*j],   ah[mt][0], ah[mt][1], ah[mt][2], ah[mt][3], bl[j][0], bl[j][2]);
                    mma16816(acc[mt][2*j],   al[mt][0], al[mt][1], al[mt][2], al[mt][3], bh[j][0], bh[j][2]);
                    mma16816(acc[mt][2*j+1], ah[mt][0], ah[mt][1], ah[mt][2], ah[mt][3], bh[j][1], bh[j][3]);
                    mma16816(acc[mt][2*j+1], ah[mt][0], ah[mt][1], ah[mt][2], ah[mt][3], bl[j][1], bl[j][3]);
                    mma16816(acc[mt][2*j+1], al[mt][0], al[mt][1], al[mt][2], al[mt][3], bh[j][1], bh[j][3]);
                }
        }
        __syncthreads();
    }

    // epilogue: direct float2 stores
    #pragma unroll
    for (int mt = 0; mt < 2; mt++) {
        int row = m0 + wm * 32 + mt * 16 + (lid >> 2);
        #pragma unroll
        for (int nt = 0; nt < 8; nt++) {
            int col = n0 + wn * 64 + nt * 8 + 2 * (lid & 3);
            float2 v0 = {acc[mt][nt][0], acc[mt][nt][1]};
            float2 v1 = {acc[mt][nt][2], acc[mt][nt][3]};
            *(float2*)&g_gx[(size_t)row * G3 + col]       = v0;
            *(float2*)&g_gx[(size_t)(row + 8) * G3 + col] = v1;
        }
    }
}

// ---------------- persistent GRU recurrence (unchanged, verified R2) ----------
#define WS_LDW 516
#define PERS_SMEM (2 * 24 * WS_LDW * 4)

__device__ __forceinline__ void load_group(const unsigned* __restrict__ hhi,
                                           const unsigned* __restrict__ hlo,
                                           int rA512, int rB512, int gi, int l4,
                                           unsigned R[4][8]) {
    #pragma unroll
    for (int c = 0; c < 4; c++) {
        int wb = gi * 32 + c * 8 + l4;
        R[c][0] = hhi[rA512 + wb];     R[c][1] = hhi[rB512 + wb];
        R[c][2] = hhi[rA512 + wb + 4]; R[c][3] = hhi[rB512 + wb + 4];
        R[c][4] = hlo[rA512 + wb];     R[c][5] = hlo[rB512 + wb];
        R[c][6] = hlo[rA512 + wb + 4]; R[c][7] = hlo[rB512 + wb + 4];
    }
}

__device__ __forceinline__ void mma_group(const unsigned* __restrict__ ws_hi,
                                          const unsigned* __restrict__ ws_lo,
                                          int gi, int l4, int n,
                                          unsigned R[4][8], float acc[3][4]) {
    #pragma unroll
    for (int c = 0; c < 4; c++) {
        int kw = gi * 32 + c * 8;
        #pragma unroll
        for (int g = 0; g < 3; g++) {
            int rowoff = (g * 8 + n) * WS_LDW + kw;
            unsigned bh0 = ws_hi[rowoff + l4],     bh1 = ws_hi[rowoff + 4 + l4];
            unsigned bl0 = ws_lo[rowoff + l4],     bl1 = ws_lo[rowoff + 4 + l4];
            mma16816(acc[g], R[c][0], R[c][1], R[c][2], R[c][3], bh0, bh1);
            mma16816(acc[g], R[c][0], R[c][1], R[c][2], R[c][3], bl0, bl1);
            mma16816(acc[g], R[c][4], R[c][5], R[c][6], R[c][7], bh0, bh1);
        }
    }
}

__device__ __forceinline__ void grid_bar(unsigned target) {
    __threadfence();
    __syncthreads();
    if (threadIdx.x == 0) {
        atomicAdd(&g_count, 1u);
        while (*(volatile unsigned*)&g_count < target) __nanosleep(20);
        __threadfence();
    }
    __syncthreads();
}

__device__ __forceinline__ float sig(float x) { return 1.0f / (1.0f + __expf(-x)); }

__global__ __launch_bounds__(256) void k_gru_persist(
        const float* __restrict__ h0, const float* __restrict__ bih,
        const float* __restrict__ bhh, float* __restrict__ out, int wh)
{
    extern __shared__ unsigned wsm[];
    unsigned* ws_hi = wsm;
    unsigned* ws_lo = wsm + 24 * WS_LDW;

    const int tid = threadIdx.x, w = tid >> 5, l = tid & 31;
    const int l4 = l & 3, n = l >> 2;
    const int j0 = blockIdx.x * 8;

    const unsigned* whh_hi32 = (const unsigned*)g_whh_hi;
    const unsigned* whh_lo32 = (const unsigned*)g_whh_lo;
    for (int i = tid; i < 24 * 512; i += 256) {
        int rr = i >> 9, kk = i & 511;
        int g = rr >> 3, jr = rr & 7;
        size_t src = (size_t)(g * 1024 + j0 + jr) * 512 + kk;
        ws_hi[rr * WS_LDW + kk] = whh_hi32[src];
        ws_lo[rr * WS_LDW + kk] = whh_lo32[src];
    }

    const int rA = w * 16 + n, rB = rA + 8;
    const int rA512 = rA * 512, rB512 = rB * 512;
    const int jc = j0 + l4 * 2;

    float bi[3][2], bh[3][2];
    #pragma unroll
    for (int g = 0; g < 3; g++) {
        bi[g][0] = bih[g * 1024 + jc]; bi[g][1] = bih[g * 1024 + jc + 1];
        bh[g][0] = bhh[g * 1024 + jc]; bh[g][1] = bhh[g * 1024 + jc + 1];
    }

    float hA0 = h0[rA * H_DIM + jc], hA1 = h0[rA * H_DIM + jc + 1];
    float hB0 = h0[rB * H_DIM + jc], hB1 = h0[rB * H_DIM + jc + 1];

    auto wr_h = [&](unsigned* dhi, unsigned* dlo, int r512, float v0, float v1) {
        __nv_bfloat162 ph, pl;
        ph.x = __float2bfloat16(v0); ph.y = __float2bfloat16(v1);
        pl.x = __float2bfloat16(v0 - __bfloat162float(ph.x));
        pl.y = __float2bfloat16(v1 - __bfloat162float(ph.y));
        dhi[r512 + (jc >> 1)] = *(unsigned*)&ph;
        dlo[r512 + (jc >> 1)] = *(unsigned*)&pl;
    };

    wr_h((unsigned*)g_hhi[0], (unsigned*)g_hlo[0], rA512, hA0, hA1);
    wr_h((unsigned*)g_hhi[0], (unsigned*)g_hlo[0], rB512, hB0, hB1);
    grid_bar(NBLK);

    unsigned tgt = 2 * NBLK;
    for (int t = 0; t < T_STEPS; t++) {
        const unsigned* hhi = (const unsigned*)g_hhi[t & 1];
        const unsigned* hlo = (const unsigned*)g_hlo[t & 1];
        unsigned* nhhi = (unsigned*)g_hhi[(t + 1) & 1];
        unsigned* nhlo = (unsigned*)g_hlo[(t + 1) & 1];
        const float* gx = g_gx + (size_t)t * B_SZ * G3;

        float2 xA[3], xB[3];
        #pragma unroll
        for (int g = 0; g < 3; g++) {
            xA[g] = *(const float2*)&gx[(size_t)rA * G3 + g * 1024 + jc];
            xB[g] = *(const float2*)&gx[(size_t)rB * G3 + g * 1024 + jc];
        }

        float acc[3][4];
        #pragma unroll
        for (int g = 0; g < 3; g++)
            #pragma unroll
            for (int c = 0; c < 4; c++) acc[g][c] = 0.0f;

        unsigned Ra[4][8], Rb[4][8];
        load_group(hhi, hlo, rA512, rB512, 0, l4, Ra);
        #pragma unroll 1
        for (int gi = 0; gi < 16; gi += 2) {
            if (gi + 1 < 16) load_group(hhi, hlo, rA512, rB512, gi + 1, l4, Rb);
            mma_group(ws_hi, ws_lo, gi, l4, n, Ra, acc);
            if (gi + 2 < 16) load_group(hhi, hlo, rA512, rB512, gi + 2, l4, Ra);
            if (gi + 1 < 16) mma_group(ws_hi, ws_lo, gi + 1, l4, n, Rb, acc);
        }

        {
            float r0 = sig(xA[0].x + bi[0][0] + acc[0][0] + bh[0][0]);
            float z0 = sig(xA[1].x + bi[1][0] + acc[1][0] + bh[1][0]);
            float n0 = tanhf(xA[2].x + bi[2][0] + r0 * (acc[2][0] + bh[2][0]));
            hA0 = (1.0f - z0) * n0 + z0 * hA0;
            float r1 = sig(xA[0].y + bi[0][1] + acc[0][1] + bh[0][1]);
            float z1 = sig(xA[1].y + bi[1][1] + acc[1][1] + bh[1][1]);
            float n1 = tanhf(xA[2].y + bi[2][1] + r1 * (acc[2][1] + bh[2][1]));
            hA1 = (1.0f - z1) * n1 + z1 * hA1;
            float r2 = sig(xB[0].x + bi[0][0] + acc[0][2] + bh[0][0]);
            float z2 = sig(xB[1].x + bi[1][0] + acc[1][2] + bh[1][0]);
            float n2 = tanhf(xB[2].x + bi[2][0] + r2 * (acc[2][2] + bh[2][0]));
            hB0 = (1.0f - z2) * n2 + z2 * hB0;
            float r3 = sig(xB[0].y + bi[0][1] + acc[0][3] + bh[0][1]);
            float z3 = sig(xB[1].y + bi[1][1] + acc[1][3] + bh[1][1]);
            float n3 = tanhf(xB[2].y + bi[2][1] + r3 * (acc[2][3] + bh[2][1]));
            hB1 = (1.0f - z3) * n3 + z3 * hB1;
        }

        float2 oA = {hA0, hA1}, oB = {hB0, hB1};
        *(float2*)&out[((size_t)t * B_SZ + rA) * H_DIM + jc] = oA;
        *(float2*)&out[((size_t)t * B_SZ + rB) * H_DIM + jc] = oB;
        wr_h(nhhi, nhlo, rA512, hA0, hA1);
        wr_h(nhhi, nhlo, rB512, hB0, hB1);
        if (t == T_STEPS - 1 && wh) {
            *(float2*)&out[(size_t)M_TOT * H_DIM + (size_t)rA * H_DIM + jc] = oA;
            *(float2*)&out[(size_t)M_TOT * H_DIM + (size_t)rB * H_DIM + jc] = oB;
        }

        grid_bar(tgt);
        tgt += NBLK;
    }
}

// ---------------- launch ------------------------------------------------------
extern "C" void kernel_launch(void* const* d_in, const int* in_sizes, int n_in,
                              void* d_out, int out_size) {
    const float* seq  = (const float*)d_in[0];
    const float* word = (const float*)d_in[1];
    const float* h0   = (const float*)d_in[2];
    const float* wih  = (const float*)d_in[3];
    const float* whh  = (const float*)d_in[4];
    const float* bih  = (const float*)d_in[5];
    const float* bhh  = (const float*)d_in[6];
    float* out = (float*)d_out;
    (void)in_sizes; (void)n_in;

    cudaFuncSetAttribute(k_gx_mma, cudaFuncAttributeMaxDynamicSharedMemorySize, GXS_SMEM);
    cudaFuncSetAttribute(k_gru_persist, cudaFuncAttributeMaxDynamicSharedMemorySize, PERS_SMEM);

    const int hidden_ok = (out_size >= T_STEPS * B_SZ * H_DIM + B_SZ * H_DIM) ? 1 : 0;

    k_init<<<1, 32>>>();
    k_split_whh<<<(G3 * H_DIM + 255) / 256, 256>>>(whh);
    k_split_wih<<<(G3 * KIN + 255) / 256, 256>>>(wih);
    k_split_x<<<(int)(((size_t)M_TOT * KIN / 4 + 255) / 256), 256>>>(seq, word);

    k_gx_mma<<<dim3(G3 / 128, M_TOT / 128), 256, GXS_SMEM>>>();

    k_gru_persist<<<NBLK, 256, PERS_SMEM>>>(h0, bih, bhh, out, hidden_ok);
}

// round 5
// speedup vs baseline: 1.6300x; 1.6300x over previous
#include <cuda_runtime.h>
#include <cuda_fp16.h>
#include <cstdint>
#include <cstddef>

#define T_STEPS 512
#define B_SZ    128
#define E_SEQ   768
#define COND    256
#define H_DIM   1024
#define KSEQ    768
#define G3      3072
#define M_TOT   (T_STEPS * B_SZ)
#define NBLK    128

// ---------------- static device scratch --------------------------------------
__device__ float   g_gx[(size_t)M_TOT * G3];          // seq-part preacts, fp32
__device__ float   g_gw[(size_t)B_SZ * G3];           // word-part preacts (t-invariant)
__device__ __half  g_whh_hi[(size_t)G3 * H_DIM];
__device__ __half  g_whh_lo[(size_t)G3 * H_DIM];
__device__ __half  g_wih_hi[(size_t)G3 * KSEQ];       // seq columns of W_ih only
__device__ __half  g_wih_lo[(size_t)G3 * KSEQ];
__device__ __half  g_xh[(size_t)M_TOT * KSEQ];        // seq activations, single fp16
__device__ __half  g_hf[2][B_SZ * H_DIM];             // double-buffered fp16 h
__device__ unsigned g_count;

// ---------------- prep kernels ------------------------------------------------
__global__ void k_init() { if (threadIdx.x == 0 && blockIdx.x == 0) g_count = 0; }

__global__ void k_split_whh(const float* __restrict__ w) {
    int i = blockIdx.x * blockDim.x + threadIdx.x;
    if (i < G3 * H_DIM) {
        float v = w[i];
        __half hi = __float2half(v);
        g_whh_hi[i] = hi;
        g_whh_lo[i] = __float2half(v - __half2float(hi));
    }
}
__global__ void k_split_wih(const float* __restrict__ w) {
    int i = blockIdx.x * blockDim.x + threadIdx.x;
    if (i < G3 * KSEQ) {
        int j = i / KSEQ, k = i - j * KSEQ;
        float v = w[(size_t)j * (COND + KSEQ) + COND + k];
        __half hi = __float2half(v);
        g_wih_hi[i] = hi;
        g_wih_lo[i] = __float2half(v - __half2float(hi));
    }
}
__global__ void k_xh(const float* __restrict__ seq) {
    size_t i = (size_t)blockIdx.x * blockDim.x + threadIdx.x;
    if (i >= (size_t)M_TOT * KSEQ / 4) return;
    float4 v = ((const float4*)seq)[i];
    __half2 p0 = {__float2half(v.x), __float2half(v.y)};
    __half2 p1 = {__float2half(v.z), __float2half(v.w)};
    ((__half2*)g_xh)[2 * i]     = p0;
    ((__half2*)g_xh)[2 * i + 1] = p1;
}
// word-part: gw[b][j] = sum_k word[b][k] * W_ih[j][k], fp32, computed once
__global__ __launch_bounds__(256) void k_word(const float* __restrict__ word,
                                              const float* __restrict__ wih) {
    __shared__ float wrow[COND];
    const int b = blockIdx.x, tid = threadIdx.x;
    if (tid < COND) wrow[tid] = word[b * COND + tid];
    __syncthreads();
    for (int j = tid; j < G3; j += 256) {
        const float4* wr = (const float4*)&wih[(size_t)j * (COND + KSEQ)];
        float s = 0.0f;
        #pragma unroll 8
        for (int k = 0; k < COND / 4; k++) {
            float4 wv = wr[k];
            s += wv.x * wrow[4*k] + wv.y * wrow[4*k+1] + wv.z * wrow[4*k+2] + wv.w * wrow[4*k+3];
        }
        g_gw[(size_t)b * G3 + j] = s;
    }
}

// ---------------- PTX helpers --------------------------------------------------
__device__ __forceinline__ unsigned smem_u32(const void* p) {
    return (unsigned)__cvta_generic_to_shared(p);
}
__device__ __forceinline__ void cp16(unsigned dst, const void* src) {
    asm volatile("cp.async.cg.shared.global [%0], [%1], 16;\n" :: "r"(dst), "l"(src));
}
#define CP_COMMIT()  asm volatile("cp.async.commit_group;\n")
#define CP_WAIT(n)   asm volatile("cp.async.wait_group %0;\n" :: "n"(n))

__device__ __forceinline__ void ldm4(unsigned r[4], unsigned addr) {
    asm volatile("ldmatrix.sync.aligned.m8n8.x4.shared.b16 {%0,%1,%2,%3}, [%4];"
        : "=r"(r[0]), "=r"(r[1]), "=r"(r[2]), "=r"(r[3]) : "r"(addr));
}
__device__ __forceinline__ void mmaf16(float c[4], unsigned a0, unsigned a1,
                                       unsigned a2, unsigned a3,
                                       unsigned b0, unsigned b1) {
    asm volatile(
        "mma.sync.aligned.m16n8k16.row.col.f32.f16.f16.f32 "
        "{%0,%1,%2,%3},{%4,%5,%6,%7},{%8,%9},{%0,%1,%2,%3};\n"
        : "+f"(c[0]), "+f"(c[1]), "+f"(c[2]), "+f"(c[3])
        : "r"(a0), "r"(a1), "r"(a2), "r"(a3), "r"(b0), "r"(b1));
}

// ---------------- gx GEMM (seq part): 128x128 CTA, 2-term fp16 ----------------
// Stage = 3 tiles (X, Whi, Wlo) x 128 rows x 144B = 55296 B; 2 stages = 110592.
#define ROWB    144
#define TILEB   (128 * ROWB)
#define STAGEB  (3 * TILEB)
#define GXS_SMEM (2 * STAGEB)

__global__ __launch_bounds__(256, 2) void k_gx_mma() {
    extern __shared__ __align__(16) char dyn[];
    const unsigned dynb = smem_u32(dyn);

    const int tid = threadIdx.x;
    const int wid = tid >> 5, lid = tid & 31;
    const int wm = wid & 3, wn = wid >> 2;           // 4x2 warps: 32m x 64n each
    const int n0 = blockIdx.x * 128;
    const int m0 = blockIdx.y * 128;

    float acc[2][8][4];
    #pragma unroll
    for (int mt = 0; mt < 2; mt++)
        #pragma unroll
        for (int nt = 0; nt < 8; nt++)
            #pragma unroll
            for (int c = 0; c < 4; c++) acc[mt][nt][c] = 0.0f;

    auto load_chunk = [&](int c, int s) {
        const int k0 = c * 64;
        const unsigned sb = dynb + s * STAGEB;
        #pragma unroll
        for (int it = 0; it < 12; it++) {
            int i = tid + it * 256;          // 0..3071
            int t = i >> 10;                 // 0..2
            int r = (i >> 3) & 127;
            int q = i & 7;
            const __half* src;
            if      (t == 0) src = g_xh     + (size_t)(m0 + r) * KSEQ + k0 + q * 8;
            else if (t == 1) src = g_wih_hi + (size_t)(n0 + r) * KSEQ + k0 + q * 8;
            else             src = g_wih_lo + (size_t)(n0 + r) * KSEQ + k0 + q * 8;
            cp16(sb + t * TILEB + r * ROWB + q * 16, src);
        }
        CP_COMMIT();
    };

    const int lrow = lid & 15;
    const int lcol = (lid >> 4) * 16;

    load_chunk(0, 0);

    for (int c = 0; c < 12; c++) {
        if (c < 11) { load_chunk(c + 1, (c + 1) & 1); CP_WAIT(1); }
        else        { CP_WAIT(0); }
        __syncthreads();

        const unsigned sb  = dynb + (c & 1) * STAGEB;
        const unsigned aX  = sb;
        const unsigned bHi = sb + TILEB;
        const unsigned bLo = sb + 2 * TILEB;

        #pragma unroll
        for (int k16 = 0; k16 < 4; k16++) {
            const unsigned kb = k16 * 32 + lcol;
            unsigned a[2][4];
            #pragma unroll
            for (int mt = 0; mt < 2; mt++)
                ldm4(a[mt], aX + (wm * 32 + mt * 16 + lrow) * ROWB + kb);
            #pragma unroll
            for (int term = 0; term < 2; term++) {
                const unsigned bb = term ? bLo : bHi;
                unsigned b[4][4];
                #pragma unroll
                for (int j = 0; j < 4; j++)
                    ldm4(b[j], bb + (wn * 64 + j * 16 + lrow) * ROWB + kb);
                #pragma unroll
                for (int mt = 0; mt < 2; mt++)
                    #pragma unroll
                    for (int j = 0; j < 4; j++) {
                        mmaf16(acc[mt][2*j],   a[mt][0], a[mt][1], a[mt][2], a[mt][3], b[j][0], b[j][2]);
                        mmaf16(acc[mt][2*j+1], a[mt][0], a[mt][1], a[mt][2], a[mt][3], b[j][1], b[j][3]);
                    }
            }
        }
        __syncthreads();
    }

    #pragma unroll
    for (int mt = 0; mt < 2; mt++) {
        int row = m0 + wm * 32 + mt * 16 + (lid >> 2);
        #pragma unroll
        for (int nt = 0; nt < 8; nt++) {
            int col = n0 + wn * 64 + nt * 8 + 2 * (lid & 3);
            float2 v0 = {acc[mt][nt][0], acc[mt][nt][1]};
            float2 v1 = {acc[mt][nt][2], acc[mt][nt][3]};
            *(float2*)&g_gx[(size_t)row * G3 + col]       = v0;
            *(float2*)&g_gx[(size_t)(row + 8) * G3 + col] = v1;
        }
    }
}

// ---------------- persistent GRU recurrence (2-term fp16) ----------------------
#define WS_LDW 516
#define PERS_SMEM (2 * 24 * WS_LDW * 4)      // 99072 B

__device__ __forceinline__ void load_group(const unsigned* __restrict__ h,
                                           int rA512, int rB512, int gi, int l4,
                                           unsigned R[4][4]) {
    #pragma unroll
    for (int c = 0; c < 4; c++) {
        int wb = gi * 32 + c * 8 + l4;
        R[c][0] = h[rA512 + wb];     R[c][1] = h[rB512 + wb];
        R[c][2] = h[rA512 + wb + 4]; R[c][3] = h[rB512 + wb + 4];
    }
}

__device__ __forceinline__ void mma_group(const unsigned* __restrict__ ws_hi,
                                          const unsigned* __restrict__ ws_lo,
                                          int gi, int l4, int n,
                                          unsigned R[4][4], float acc[3][4]) {
    #pragma unroll
    for (int c = 0; c < 4; c++) {
        int kw = gi * 32 + c * 8;
        unsigned bh[3][2], bl[3][2];
        #pragma unroll
        for (int g = 0; g < 3; g++) {
            int rowoff = (g * 8 + n) * WS_LDW + kw;
            bh[g][0] = ws_hi[rowoff + l4]; bh[g][1] = ws_hi[rowoff + 4 + l4];
            bl[g][0] = ws_lo[rowoff + l4]; bl[g][1] = ws_lo[rowoff + 4 + l4];
        }
        #pragma unroll
        for (int g = 0; g < 3; g++)
            mmaf16(acc[g], R[c][0], R[c][1], R[c][2], R[c][3], bh[g][0], bh[g][1]);
        #pragma unroll
        for (int g = 0; g < 3; g++)
            mmaf16(acc[g], R[c][0], R[c][1], R[c][2], R[c][3], bl[g][0], bl[g][1]);
    }
}

__device__ __forceinline__ void grid_bar(unsigned target) {
    __threadfence();
    __syncthreads();
    if (threadIdx.x == 0) {
        atomicAdd(&g_count, 1u);
        while (*(volatile unsigned*)&g_count < target) __nanosleep(20);
        __threadfence();
    }
    __syncthreads();
}

__device__ __forceinline__ float sig(float x) { return 1.0f / (1.0f + __expf(-x)); }

__global__ __launch_bounds__(256) void k_gru_persist(
        const float* __restrict__ h0, const float* __restrict__ bih,
        const float* __restrict__ bhh, float* __restrict__ out, int wh)
{
    extern __shared__ unsigned wsm[];
    unsigned* ws_hi = wsm;
    unsigned* ws_lo = wsm + 24 * WS_LDW;

    const int tid = threadIdx.x, w = tid >> 5, l = tid & 31;
    const int l4 = l & 3, n = l >> 2;
    const int j0 = blockIdx.x * 8;

    const unsigned* whh_hi32 = (const unsigned*)g_whh_hi;
    const unsigned* whh_lo32 = (const unsigned*)g_whh_lo;
    for (int i = tid; i < 24 * 512; i += 256) {
        int rr = i >> 9, kk = i & 511;
        int g = rr >> 3, jr = rr & 7;
        size_t src = (size_t)(g * 1024 + j0 + jr) * 512 + kk;
        ws_hi[rr * WS_LDW + kk] = whh_hi32[src];
        ws_lo[rr * WS_LDW + kk] = whh_lo32[src];
    }

    const int rA = w * 16 + n, rB = rA + 8;
    const int rA512 = rA * 512, rB512 = rB * 512;
    const int jc = j0 + l4 * 2;

    // biases + t-invariant word-part preacts, folded per row
    float biA[3][2], biB[3][2], bh[3][2];
    #pragma unroll
    for (int g = 0; g < 3; g++) {
        float b0 = bih[g * 1024 + jc], b1 = bih[g * 1024 + jc + 1];
        biA[g][0] = b0 + g_gw[(size_t)rA * G3 + g * 1024 + jc];
        biA[g][1] = b1 + g_gw[(size_t)rA * G3 + g * 1024 + jc + 1];
        biB[g][0] = b0 + g_gw[(size_t)rB * G3 + g * 1024 + jc];
        biB[g][1] = b1 + g_gw[(size_t)rB * G3 + g * 1024 + jc + 1];
        bh[g][0] = bhh[g * 1024 + jc]; bh[g][1] = bhh[g * 1024 + jc + 1];
    }

    float hA0 = h0[rA * H_DIM + jc], hA1 = h0[rA * H_DIM + jc + 1];
    float hB0 = h0[rB * H_DIM + jc], hB1 = h0[rB * H_DIM + jc + 1];

    auto wr_h = [&](unsigned* dst, int r512, float v0, float v1) {
        __half2 p = {__float2half(v0), __float2half(v1)};
        dst[r512 + (jc >> 1)] = *(unsigned*)&p;
    };

    wr_h((unsigned*)g_hf[0], rA512, hA0, hA1);
    wr_h((unsigned*)g_hf[0], rB512, hB0, hB1);
    grid_bar(NBLK);

    unsigned tgt = 2 * NBLK;
    for (int t = 0; t < T_STEPS; t++) {
        const unsigned* hcur = (const unsigned*)g_hf[t & 1];
        unsigned* hnxt       = (unsigned*)g_hf[(t + 1) & 1];
        const float* gx = g_gx + (size_t)t * B_SZ * G3;

        float2 xA[3], xB[3];
        #pragma unroll
        for (int g = 0; g < 3; g++) {
            xA[g] = *(const float2*)&gx[(size_t)rA * G3 + g * 1024 + jc];
            xB[g] = *(const float2*)&gx[(size_t)rB * G3 + g * 1024 + jc];
        }

        float acc[3][4];
        #pragma unroll
        for (int g = 0; g < 3; g++)
            #pragma unroll
            for (int c = 0; c < 4; c++) acc[g][c] = 0.0f;

        unsigned Ra[4][4], Rb[4][4];
        load_group(hcur, rA512, rB512, 0, l4, Ra);
        #pragma unroll 1
        for (int gi = 0; gi < 16; gi += 2) {
            if (gi + 1 < 16) load_group(hcur, rA512, rB512, gi + 1, l4, Rb);
            mma_group(ws_hi, ws_lo, gi, l4, n, Ra, acc);
            if (gi + 2 < 16) load_group(hcur, rA512, rB512, gi + 2, l4, Ra);
            if (gi + 1 < 16) mma_group(ws_hi, ws_lo, gi + 1, l4, n, Rb, acc);
        }

        {
            float r0 = sig(xA[0].x + biA[0][0] + acc[0][0] + bh[0][0]);
            float z0 = sig(xA[1].x + biA[1][0] + acc[1][0] + bh[1][0]);
            float n0 = tanhf(xA[2].x + biA[2][0] + r0 * (acc[2][0] + bh[2][0]));
            hA0 = (1.0f - z0) * n0 + z0 * hA0;
            float r1 = sig(xA[0].y + biA[0][1] + acc[0][1] + bh[0][1]);
            float z1 = sig(xA[1].y + biA[1][1] + acc[1][1] + bh[1][1]);
            float n1 = tanhf(xA[2].y + biA[2][1] + r1 * (acc[2][1] + bh[2][1]));
            hA1 = (1.0f - z1) * n1 + z1 * hA1;
            float r2 = sig(xB[0].x + biB[0][0] + acc[0][2] + bh[0][0]);
            float z2 = sig(xB[1].x + biB[1][0] + acc[1][2] + bh[1][0]);
            float n2 = tanhf(xB[2].x + biB[2][0] + r2 * (acc[2][2] + bh[2][0]));
            hB0 = (1.0f - z2) * n2 + z2 * hB0;
            float r3 = sig(xB[0].y + biB[0][1] + acc[0][3] + bh[0][1]);
            float z3 = sig(xB[1].y + biB[1][1] + acc[1][3] + bh[1][1]);
            float n3 = tanhf(xB[2].y + biB[2][1] + r3 * (acc[2][3] + bh[2][1]));
            hB1 = (1.0f - z3) * n3 + z3 * hB1;
        }

        float2 oA = {hA0, hA1}, oB = {hB0, hB1};
        *(float2*)&out[((size_t)t * B_SZ + rA) * H_DIM + jc] = oA;
        *(float2*)&out[((size_t)t * B_SZ + rB) * H_DIM + jc] = oB;
        wr_h(hnxt, rA512, hA0, hA1);
        wr_h(hnxt, rB512, hB0, hB1);
        if (t == T_STEPS - 1 && wh) {
            *(float2*)&out[(size_t)M_TOT * H_DIM + (size_t)rA * H_DIM + jc] = oA;
            *(float2*)&out[(size_t)M_TOT * H_DIM + (size_t)rB * H_DIM + jc] = oB;
        }

        grid_bar(tgt);
        tgt += NBLK;
    }
}

// ---------------- launch ------------------------------------------------------
extern "C" void kernel_launch(void* const* d_in, const int* in_sizes, int n_in,
                              void* d_out, int out_size) {
    const float* seq  = (const float*)d_in[0];
    const float* word = (const float*)d_in[1];
    const float* h0   = (const float*)d_in[2];
    const float* wih  = (const float*)d_in[3];
    const float* whh  = (const float*)d_in[4];
    const float* bih  = (const float*)d_in[5];
    const float* bhh  = (const float*)d_in[6];
    float* out = (float*)d_out;
    (void)in_sizes; (void)n_in;

    cudaFuncSetAttribute(k_gx_mma, cudaFuncAttributeMaxDynamicSharedMemorySize, GXS_SMEM);
    cudaFuncSetAttribute(k_gru_persist, cudaFuncAttributeMaxDynamicSharedMemorySize, PERS_SMEM);

    const int hidden_ok = (out_size >= T_STEPS * B_SZ * H_DIM + B_SZ * H_DIM) ? 1 : 0;

    k_init<<<1, 32>>>();
    k_split_whh<<<(G3 * H_DIM + 255) / 256, 256>>>(whh);
    k_split_wih<<<(G3 * KSEQ + 255) / 256, 256>>>(wih);
    k_xh<<<(int)(((size_t)M_TOT * KSEQ / 4 + 255) / 256), 256>>>(seq);
    k_word<<<B_SZ, 256>>>(word, wih);

    k_gx_mma<<<dim3(G3 / 128, M_TOT / 128), 256, GXS_SMEM>>>();

    k_gru_persist<<<NBLK, 256, PERS_SMEM>>>(h0, bih, bhh, out, hidden_ok);
}

// round 6
// speedup vs baseline: 1.9849x; 1.2177x over previous
#include <cuda_runtime.h>
#include <cuda_fp16.h>
#include <cstdint>
#include <cstddef>

#define T_STEPS 512
#define B_SZ    128
#define E_SEQ   768
#define COND    256
#define H_DIM   1024
#define KSEQ    768
#define G3      3072
#define M_TOT   (T_STEPS * B_SZ)
#define NBLK    128

// ---------------- static device scratch --------------------------------------
__device__ float   g_gx[(size_t)M_TOT * G3];          // seq-part preacts, fp32
__device__ float   g_gw[(size_t)B_SZ * G3];           // word-part preacts (t-invariant)
__device__ __half  g_whh[(size_t)G3 * H_DIM];         // single fp16 weights
__device__ __half  g_wih[(size_t)G3 * KSEQ];          // seq columns of W_ih, fp16
__device__ __half  g_xh[(size_t)M_TOT * KSEQ];        // seq activations, fp16
__device__ __half  g_hf[2][B_SZ * H_DIM];             // double-buffered fp16 h
__device__ unsigned g_count;

// ---------------- prep kernels ------------------------------------------------
__global__ void k_init() { if (threadIdx.x == 0 && blockIdx.x == 0) g_count = 0; }

__global__ void k_cvt_whh(const float* __restrict__ w) {
    int i = blockIdx.x * blockDim.x + threadIdx.x;
    if (i < G3 * H_DIM) g_whh[i] = __float2half(w[i]);
}
__global__ void k_cvt_wih(const float* __restrict__ w) {
    int i = blockIdx.x * blockDim.x + threadIdx.x;
    if (i < G3 * KSEQ) {
        int j = i / KSEQ, k = i - j * KSEQ;
        g_wih[i] = __float2half(w[(size_t)j * (COND + KSEQ) + COND + k]);
    }
}
__global__ void k_xh(const float* __restrict__ seq) {
    size_t i = (size_t)blockIdx.x * blockDim.x + threadIdx.x;
    if (i >= (size_t)M_TOT * KSEQ / 4) return;
    float4 v = ((const float4*)seq)[i];
    __half2 p0 = {__float2half(v.x), __float2half(v.y)};
    __half2 p1 = {__float2half(v.z), __float2half(v.w)};
    ((__half2*)g_xh)[2 * i]     = p0;
    ((__half2*)g_xh)[2 * i + 1] = p1;
}
// word-part: gw[b][j] = sum_k word[b][k] * W_ih[j][k], fp32, once
__global__ __launch_bounds__(256) void k_word(const float* __restrict__ word,
                                              const float* __restrict__ wih) {
    __shared__ float wrow[COND];
    const int b = blockIdx.x, tid = threadIdx.x;
    if (tid < COND) wrow[tid] = word[b * COND + tid];
    __syncthreads();
    for (int j = tid; j < G3; j += 256) {
        const float4* wr = (const float4*)&wih[(size_t)j * (COND + KSEQ)];
        float s = 0.0f;
        #pragma unroll 8
        for (int k = 0; k < COND / 4; k++) {
            float4 wv = wr[k];
            s += wv.x * wrow[4*k] + wv.y * wrow[4*k+1] + wv.z * wrow[4*k+2] + wv.w * wrow[4*k+3];
        }
        g_gw[(size_t)b * G3 + j] = s;
    }
}

// ---------------- PTX helpers --------------------------------------------------
__device__ __forceinline__ unsigned smem_u32(const void* p) {
    return (unsigned)__cvta_generic_to_shared(p);
}
__device__ __forceinline__ void cp16(unsigned dst, const void* src) {
    asm volatile("cp.async.cg.shared.global [%0], [%1], 16;\n" :: "r"(dst), "l"(src));
}
#define CP_COMMIT()  asm volatile("cp.async.commit_group;\n")
#define CP_WAIT(n)   asm volatile("cp.async.wait_group %0;\n" :: "n"(n))

__device__ __forceinline__ void ldm4(unsigned r[4], unsigned addr) {
    asm volatile("ldmatrix.sync.aligned.m8n8.x4.shared.b16 {%0,%1,%2,%3}, [%4];"
        : "=r"(r[0]), "=r"(r[1]), "=r"(r[2]), "=r"(r[3]) : "r"(addr));
}
__device__ __forceinline__ void mmaf16(float c[4], unsigned a0, unsigned a1,
                                       unsigned a2, unsigned a3,
                                       unsigned b0, unsigned b1) {
    asm volatile(
        "mma.sync.aligned.m16n8k16.row.col.f32.f16.f16.f32 "
        "{%0,%1,%2,%3},{%4,%5,%6,%7},{%8,%9},{%0,%1,%2,%3};\n"
        : "+f"(c[0]), "+f"(c[1]), "+f"(c[2]), "+f"(c[3])
        : "r"(a0), "r"(a1), "r"(a2), "r"(a3), "r"(b0), "r"(b1));
}

// ---------------- gx GEMM (seq part): 128x128 CTA, single fp16 ----------------
// Stage = 2 tiles (X, W) x 128 rows x 144B = 36864 B; 2 stages = 73728.
#define ROWB    144
#define TILEB   (128 * ROWB)
#define STAGEB  (2 * TILEB)
#define GXS_SMEM (2 * STAGEB)

__global__ __launch_bounds__(256, 2) void k_gx_mma() {
    extern __shared__ __align__(16) char dyn[];
    const unsigned dynb = smem_u32(dyn);

    const int tid = threadIdx.x;
    const int wid = tid >> 5, lid = tid & 31;
    const int wm = wid & 3, wn = wid >> 2;           // 4x2 warps: 32m x 64n each
    const int n0 = blockIdx.x * 128;
    const int m0 = blockIdx.y * 128;

    float acc[2][8][4];
    #pragma unroll
    for (int mt = 0; mt < 2; mt++)
        #pragma unroll
        for (int nt = 0; nt < 8; nt++)
            #pragma unroll
            for (int c = 0; c < 4; c++) acc[mt][nt][c] = 0.0f;

    auto load_chunk = [&](int c, int s) {
        const int k0 = c * 64;
        const unsigned sb = dynb + s * STAGEB;
        #pragma unroll
        for (int it = 0; it < 8; it++) {
            int i = tid + it * 256;          // 0..2047
            int t = i >> 10;                 // 0..1
            int r = (i >> 3) & 127;
            int q = i & 7;
            const __half* src = (t == 0)
                ? g_xh  + (size_t)(m0 + r) * KSEQ + k0 + q * 8
                : g_wih + (size_t)(n0 + r) * KSEQ + k0 + q * 8;
            cp16(sb + t * TILEB + r * ROWB + q * 16, src);
        }
        CP_COMMIT();
    };

    const int lrow = lid & 15;
    const int lcol = (lid >> 4) * 16;

    load_chunk(0, 0);

    for (int c = 0; c < 12; c++) {
        if (c < 11) { load_chunk(c + 1, (c + 1) & 1); CP_WAIT(1); }
        else        { CP_WAIT(0); }
        __syncthreads();

        const unsigned sb = dynb + (c & 1) * STAGEB;
        const unsigned aX = sb;
        const unsigned bW = sb + TILEB;

        #pragma unroll
        for (int k16 = 0; k16 < 4; k16++) {
            const unsigned kb = k16 * 32 + lcol;
            unsigned a[2][4], b[4][4];
            #pragma unroll
            for (int mt = 0; mt < 2; mt++)
                ldm4(a[mt], aX + (wm * 32 + mt * 16 + lrow) * ROWB + kb);
            #pragma unroll
            for (int j = 0; j < 4; j++)
                ldm4(b[j], bW + (wn * 64 + j * 16 + lrow) * ROWB + kb);
            #pragma unroll
            for (int mt = 0; mt < 2; mt++)
                #pragma unroll
                for (int j = 0; j < 4; j++) {
                    mmaf16(acc[mt][2*j],   a[mt][0], a[mt][1], a[mt][2], a[mt][3], b[j][0], b[j][2]);
                    mmaf16(acc[mt][2*j+1], a[mt][0], a[mt][1], a[mt][2], a[mt][3], b[j][1], b[j][3]);
                }
        }
        __syncthreads();
    }

    #pragma unroll
    for (int mt = 0; mt < 2; mt++) {
        int row = m0 + wm * 32 + mt * 16 + (lid >> 2);
        #pragma unroll
        for (int nt = 0; nt < 8; nt++) {
            int col = n0 + wn * 64 + nt * 8 + 2 * (lid & 3);
            float2 v0 = {acc[mt][nt][0], acc[mt][nt][1]};
            float2 v1 = {acc[mt][nt][2], acc[mt][nt][3]};
            *(float2*)&g_gx[(size_t)row * G3 + col]       = v0;
            *(float2*)&g_gx[(size_t)(row + 8) * G3 + col] = v1;
        }
    }
}

// ---------------- persistent GRU recurrence (single fp16) ----------------------
#define WS_LDW 516
#define PERS_SMEM (24 * WS_LDW * 4)          // 49536 B

__device__ __forceinline__ void load_group(const unsigned* __restrict__ h,
                                           int rA512, int rB512, int gi, int l4,
                                           unsigned R[4][4]) {
    #pragma unroll
    for (int c = 0; c < 4; c++) {
        int wb = gi * 32 + c * 8 + l4;
        R[c][0] = h[rA512 + wb];     R[c][1] = h[rB512 + wb];
        R[c][2] = h[rA512 + wb + 4]; R[c][3] = h[rB512 + wb + 4];
    }
}

__device__ __forceinline__ void mma_group(const unsigned* __restrict__ ws,
                                          int gi, int l4, int n,
                                          unsigned R[4][4], float acc[3][4]) {
    #pragma unroll
    for (int c = 0; c < 4; c++) {
        int kw = gi * 32 + c * 8;
        unsigned b[3][2];
        #pragma unroll
        for (int g = 0; g < 3; g++) {
            int rowoff = (g * 8 + n) * WS_LDW + kw;
            b[g][0] = ws[rowoff + l4]; b[g][1] = ws[rowoff + 4 + l4];
        }
        #pragma unroll
        for (int g = 0; g < 3; g++)
            mmaf16(acc[g], R[c][0], R[c][1], R[c][2], R[c][3], b[g][0], b[g][1]);
    }
}

__device__ __forceinline__ void grid_bar(unsigned target) {
    __threadfence();
    __syncthreads();
    if (threadIdx.x == 0) {
        atomicAdd(&g_count, 1u);
        while (*(volatile unsigned*)&g_count < target) __nanosleep(20);
        __threadfence();
    }
    __syncthreads();
}

__device__ __forceinline__ float sig(float x) { return 1.0f / (1.0f + __expf(-x)); }

__global__ __launch_bounds__(256) void k_gru_persist(
        const float* __restrict__ h0, const float* __restrict__ bih,
        const float* __restrict__ bhh, float* __restrict__ out, int wh)
{
    extern __shared__ unsigned wsm[];
    unsigned* ws = wsm;

    const int tid = threadIdx.x, w = tid >> 5, l = tid & 31;
    const int l4 = l & 3, n = l >> 2;
    const int j0 = blockIdx.x * 8;

    const unsigned* whh32 = (const unsigned*)g_whh;
    for (int i = tid; i < 24 * 512; i += 256) {
        int rr = i >> 9, kk = i & 511;
        int g = rr >> 3, jr = rr & 7;
        ws[rr * WS_LDW + kk] = whh32[(size_t)(g * 1024 + j0 + jr) * 512 + kk];
    }

    const int rA = w * 16 + n, rB = rA + 8;
    const int rA512 = rA * 512, rB512 = rB * 512;
    const int jc = j0 + l4 * 2;

    float biA[3][2], biB[3][2], bh[3][2];
    #pragma unroll
    for (int g = 0; g < 3; g++) {
        float b0 = bih[g * 1024 + jc], b1 = bih[g * 1024 + jc + 1];
        biA[g][0] = b0 + g_gw[(size_t)rA * G3 + g * 1024 + jc];
        biA[g][1] = b1 + g_gw[(size_t)rA * G3 + g * 1024 + jc + 1];
        biB[g][0] = b0 + g_gw[(size_t)rB * G3 + g * 1024 + jc];
        biB[g][1] = b1 + g_gw[(size_t)rB * G3 + g * 1024 + jc + 1];
        bh[g][0] = bhh[g * 1024 + jc]; bh[g][1] = bhh[g * 1024 + jc + 1];
    }

    float hA0 = h0[rA * H_DIM + jc], hA1 = h0[rA * H_DIM + jc + 1];
    float hB0 = h0[rB * H_DIM + jc], hB1 = h0[rB * H_DIM + jc + 1];

    auto wr_h = [&](unsigned* dst, int r512, float v0, float v1) {
        __half2 p = {__float2half(v0), __float2half(v1)};
        dst[r512 + (jc >> 1)] = *(unsigned*)&p;
    };

    wr_h((unsigned*)g_hf[0], rA512, hA0, hA1);
    wr_h((unsigned*)g_hf[0], rB512, hB0, hB1);
    grid_bar(NBLK);

    unsigned tgt = 2 * NBLK;
    for (int t = 0; t < T_STEPS; t++) {
        const unsigned* hcur = (const unsigned*)g_hf[t & 1];
        unsigned* hnxt       = (unsigned*)g_hf[(t + 1) & 1];
        const float* gx = g_gx + (size_t)t * B_SZ * G3;

        float2 xA[3], xB[3];
        #pragma unroll
        for (int g = 0; g < 3; g++) {
            xA[g] = *(const float2*)&gx[(size_t)rA * G3 + g * 1024 + jc];
            xB[g] = *(const float2*)&gx[(size_t)rB * G3 + g * 1024 + jc];
        }

        float acc[3][4];
        #pragma unroll
        for (int g = 0; g < 3; g++)
            #pragma unroll
            for (int c = 0; c < 4; c++) acc[g][c] = 0.0f;

        unsigned Ra[4][4], Rb[4][4];
        load_group(hcur, rA512, rB512, 0, l4, Ra);
        #pragma unroll 1
        for (int gi = 0; gi < 16; gi += 2) {
            if (gi + 1 < 16) load_group(hcur, rA512, rB512, gi + 1, l4, Rb);
            mma_group(ws, gi, l4, n, Ra, acc);
            if (gi + 2 < 16) load_group(hcur, rA512, rB512, gi + 2, l4, Ra);
            if (gi + 1 < 16) mma_group(ws, gi + 1, l4, n, Rb, acc);
        }

        {
            float r0 = sig(xA[0].x + biA[0][0] + acc[0][0] + bh[0][0]);
            float z0 = sig(xA[1].x + biA[1][0] + acc[1][0] + bh[1][0]);
            float n0 = tanhf(xA[2].x + biA[2][0] + r0 * (acc[2][0] + bh[2][0]));
            hA0 = (1.0f - z0) * n0 + z0 * hA0;
            float r1 = sig(xA[0].y + biA[0][1] + acc[0][1] + bh[0][1]);
            float z1 = sig(xA[1].y + biA[1][1] + acc[1][1] + bh[1][1]);
            float n1 = tanhf(xA[2].y + biA[2][1] + r1 * (acc[2][1] + bh[2][1]));
            hA1 = (1.0f - z1) * n1 + z1 * hA1;
            float r2 = sig(xB[0].x + biB[0][0] + acc[0][2] + bh[0][0]);
            float z2 = sig(xB[1].x + biB[1][0] + acc[1][2] + bh[1][0]);
            float n2 = tanhf(xB[2].x + biB[2][0] + r2 * (acc[2][2] + bh[2][0]));
            hB0 = (1.0f - z2) * n2 + z2 * hB0;
            float r3 = sig(xB[0].y + biB[0][1] + acc[0][3] + bh[0][1]);
            float z3 = sig(xB[1].y + biB[1][1] + acc[1][3] + bh[1][1]);
            float n3 = tanhf(xB[2].y + biB[2][1] + r3 * (acc[2][3] + bh[2][1]));
            hB1 = (1.0f - z3) * n3 + z3 * hB1;
        }

        float2 oA = {hA0, hA1}, oB = {hB0, hB1};
        *(float2*)&out[((size_t)t * B_SZ + rA) * H_DIM + jc] = oA;
        *(float2*)&out[((size_t)t * B_SZ + rB) * H_DIM + jc] = oB;
        wr_h(hnxt, rA512, hA0, hA1);
        wr_h(hnxt, rB512, hB0, hB1);
        if (t == T_STEPS - 1 && wh) {
            *(float2*)&out[(size_t)M_TOT * H_DIM + (size_t)rA * H_DIM + jc] = oA;
            *(float2*)&out[(size_t)M_TOT * H_DIM + (size_t)rB * H_DIM + jc] = oB;
        }

        grid_bar(tgt);
        tgt += NBLK;
    }
}

// ---------------- launch ------------------------------------------------------
extern "C" void kernel_launch(void* const* d_in, const int* in_sizes, int n_in,
                              void* d_out, int out_size) {
    const float* seq  = (const float*)d_in[0];
    const float* word = (const float*)d_in[1];
    const float* h0   = (const float*)d_in[2];
    const float* wih  = (const float*)d_in[3];
    const float* whh  = (const float*)d_in[4];
    const float* bih  = (const float*)d_in[5];
    const float* bhh  = (const float*)d_in[6];
    float* out = (float*)d_out;
    (void)in_sizes; (void)n_in;

    cudaFuncSetAttribute(k_gx_mma, cudaFuncAttributeMaxDynamicSharedMemorySize, GXS_SMEM);
    cudaFuncSetAttribute(k_gru_persist, cudaFuncAttributeMaxDynamicSharedMemorySize, PERS_SMEM);

    const int hidden_ok = (out_size >= T_STEPS * B_SZ * H_DIM + B_SZ * H_DIM) ? 1 : 0;

    k_init<<<1, 32>>>();
    k_cvt_whh<<<(G3 * H_DIM + 255) / 256, 256>>>(whh);
    k_cvt_wih<<<(G3 * KSEQ + 255) / 256, 256>>>(wih);
    k_xh<<<(int)(((size_t)M_TOT * KSEQ / 4 + 255) / 256), 256>>>(seq);
    k_word<<<B_SZ, 256>>>(word, wih);

    k_gx_mma<<<dim3(G3 / 128, M_TOT / 128), 256, GXS_SMEM>>>();

    k_gru_persist<<<NBLK, 256, PERS_SMEM>>>(h0, bih, bhh, out, hidden_ok);
}